// round 1
// baseline (speedup 1.0000x reference)
#include <cuda_runtime.h>

#define Bsz 4
#define Hsz 16
#define Ssz 2048
#define Dsz 128
#define BM 64
#define BN 64
#define NW 8
#define NT 256
#define QS 132   // Q/K row stride in floats: 132 mod 32 = 4 -> conflict-free strided rows
#define PS 68    // P row stride: makes scatter stores conflict-free
#define NEG_INF -1e30f

struct Smem {
  float Q[BM][QS];
  float K[BN][QS];
  float V[BN][Dsz];
  float P[NW][8][PS];
};

__global__ __launch_bounds__(NT, 1) void fa_fwd(
    const float* __restrict__ gq, const float* __restrict__ gk,
    const float* __restrict__ gv, float* __restrict__ gout) {
  extern __shared__ Smem sm[];
  Smem& s = sm[0];

  const int bh = blockIdx.y;
  const int m0 = blockIdx.x * BM;
  const size_t base = (size_t)bh * Ssz * Dsz;
  const float* q = gq + base;
  const float* k = gk + base;
  const float* v = gv + base;
  float* out = gout + base;

  const int tid  = threadIdx.x;
  const int warp = tid >> 5;
  const int lane = tid & 31;
  const int lr   = lane >> 3;   // 0..3
  const int lc   = lane & 7;    // 0..7
  const int row0 = warp * 8 + lr * 2;  // tile-local rows row0, row0+1

  // ---- Load Q tile (64 x 128) ----
  for (int i = tid; i < BM * (Dsz / 4); i += NT) {
    int r = i >> 5;           // 32 float4 per row
    int c = (i & 31) * 4;
    *(float4*)&s.Q[r][c] = *(const float4*)&q[(size_t)(m0 + r) * Dsz + c];
  }

  float acc[2][16];
  float mi[2] = {NEG_INF, NEG_INF};
  float li[2] = {0.f, 0.f};
#pragma unroll
  for (int a = 0; a < 2; a++)
#pragma unroll
    for (int b = 0; b < 16; b++) acc[a][b] = 0.f;

  const int tdiag = blockIdx.x;   // BM == BN
  const float scl = 0.08838834764831845f;  // 1/sqrt(128)

  for (int t = 0; t <= tdiag; t++) {
    const int n0 = t * BN;
    __syncthreads();   // previous tile's P/V use complete
    // ---- Load K, V tiles ----
    for (int i = tid; i < BN * (Dsz / 4); i += NT) {
      int r = i >> 5;
      int c = (i & 31) * 4;
      *(float4*)&s.K[r][c] = *(const float4*)&k[(size_t)(n0 + r) * Dsz + c];
      *(float4*)&s.V[r][c] = *(const float4*)&v[(size_t)(n0 + r) * Dsz + c];
    }
    __syncthreads();

    // ---- Scores: sc[m][j] = Q[row0+m] . K[lc + 8j] ----
    float sc[2][8];
#pragma unroll
    for (int m = 0; m < 2; m++)
#pragma unroll
      for (int j = 0; j < 8; j++) sc[m][j] = 0.f;

#pragma unroll 4
    for (int kk = 0; kk < Dsz; kk += 4) {
      float4 q0 = *(const float4*)&s.Q[row0][kk];
      float4 q1 = *(const float4*)&s.Q[row0 + 1][kk];
#pragma unroll
      for (int j = 0; j < 8; j++) {
        float4 kv = *(const float4*)&s.K[lc + 8 * j][kk];
        sc[0][j] = fmaf(q0.x, kv.x, sc[0][j]);
        sc[0][j] = fmaf(q0.y, kv.y, sc[0][j]);
        sc[0][j] = fmaf(q0.z, kv.z, sc[0][j]);
        sc[0][j] = fmaf(q0.w, kv.w, sc[0][j]);
        sc[1][j] = fmaf(q1.x, kv.x, sc[1][j]);
        sc[1][j] = fmaf(q1.y, kv.y, sc[1][j]);
        sc[1][j] = fmaf(q1.z, kv.z, sc[1][j]);
        sc[1][j] = fmaf(q1.w, kv.w, sc[1][j]);
      }
    }

    // ---- Scale + causal mask (only the diagonal tile needs masking) ----
    const bool diag = (t == tdiag);
#pragma unroll
    for (int m = 0; m < 2; m++) {
      const int grow = m0 + row0 + m;
#pragma unroll
      for (int j = 0; j < 8; j++) {
        float x = sc[m][j] * scl;
        if (diag && (n0 + lc + 8 * j) > grow) x = NEG_INF;
        sc[m][j] = x;
      }
    }

    // ---- Online softmax per row ----
#pragma unroll
    for (int m = 0; m < 2; m++) {
      float mx = sc[m][0];
#pragma unroll
      for (int j = 1; j < 8; j++) mx = fmaxf(mx, sc[m][j]);
      mx = fmaxf(mx, __shfl_xor_sync(0xffffffffu, mx, 1));
      mx = fmaxf(mx, __shfl_xor_sync(0xffffffffu, mx, 2));
      mx = fmaxf(mx, __shfl_xor_sync(0xffffffffu, mx, 4));

      float mnew  = fmaxf(mi[m], mx);
      float alpha = __expf(mi[m] - mnew);
      float rs = 0.f;
#pragma unroll
      for (int j = 0; j < 8; j++) {
        float p = __expf(sc[m][j] - mnew);
        sc[m][j] = p;
        rs += p;
      }
      rs += __shfl_xor_sync(0xffffffffu, rs, 1);
      rs += __shfl_xor_sync(0xffffffffu, rs, 2);
      rs += __shfl_xor_sync(0xffffffffu, rs, 4);

      li[m] = li[m] * alpha + rs;
      mi[m] = mnew;
#pragma unroll
      for (int c = 0; c < 16; c++) acc[m][c] *= alpha;

      // stage P for the PV matmul (conflict-free scatter with PS=68)
#pragma unroll
      for (int j = 0; j < 8; j++) s.P[warp][lr * 2 + m][lc + 8 * j] = sc[m][j];
    }
    __syncwarp();

    // ---- acc += P @ V ----
#pragma unroll 2
    for (int n = 0; n < BN; n++) {
      float p0 = s.P[warp][lr * 2 + 0][n];
      float p1 = s.P[warp][lr * 2 + 1][n];
#pragma unroll
      for (int c = 0; c < 4; c++) {
        float4 vv = *(const float4*)&s.V[n][lc * 4 + c * 32];
        acc[0][c * 4 + 0] = fmaf(p0, vv.x, acc[0][c * 4 + 0]);
        acc[0][c * 4 + 1] = fmaf(p0, vv.y, acc[0][c * 4 + 1]);
        acc[0][c * 4 + 2] = fmaf(p0, vv.z, acc[0][c * 4 + 2]);
        acc[0][c * 4 + 3] = fmaf(p0, vv.w, acc[0][c * 4 + 3]);
        acc[1][c * 4 + 0] = fmaf(p1, vv.x, acc[1][c * 4 + 0]);
        acc[1][c * 4 + 1] = fmaf(p1, vv.y, acc[1][c * 4 + 1]);
        acc[1][c * 4 + 2] = fmaf(p1, vv.z, acc[1][c * 4 + 2]);
        acc[1][c * 4 + 3] = fmaf(p1, vv.w, acc[1][c * 4 + 3]);
      }
    }
  }

  // ---- Epilogue: normalize and store ----
#pragma unroll
  for (int m = 0; m < 2; m++) {
    float inv = 1.0f / li[m];
    size_t rowaddr = (size_t)(m0 + row0 + m) * Dsz;
#pragma unroll
    for (int c = 0; c < 4; c++) {
      float4 o;
      o.x = acc[m][c * 4 + 0] * inv;
      o.y = acc[m][c * 4 + 1] * inv;
      o.z = acc[m][c * 4 + 2] * inv;
      o.w = acc[m][c * 4 + 3] * inv;
      *(float4*)&out[rowaddr + lc * 4 + c * 32] = o;
    }
  }
}

extern "C" void kernel_launch(void* const* d_in, const int* in_sizes, int n_in,
                              void* d_out, int out_size) {
  // q, k, v are the three inputs with B*H*S*D elements (mask has S*S, skip it)
  const int qkv_elems = Bsz * Hsz * Ssz * Dsz;  // 16777216
  const float* ptrs[3] = {nullptr, nullptr, nullptr};
  int np = 0;
  for (int i = 0; i < n_in && np < 3; i++) {
    if (in_sizes[i] == qkv_elems) ptrs[np++] = (const float*)d_in[i];
  }

  size_t smem_bytes = sizeof(Smem);
  cudaFuncSetAttribute(fa_fwd, cudaFuncAttributeMaxDynamicSharedMemorySize,
                       (int)smem_bytes);

  dim3 grid(Ssz / BM, Bsz * Hsz);
  fa_fwd<<<grid, NT, smem_bytes>>>(ptrs[0], ptrs[1], ptrs[2], (float*)d_out);
}

// round 2
// speedup vs baseline: 3.1272x; 3.1272x over previous
#include <cuda_runtime.h>
#include <cstdint>

#define Bsz 4
#define Hsz 16
#define Ssz 2048
#define Dsz 128
#define BM 128
#define BN 64
#define NW 4
#define NT 128
#define QSTR 132   // banks (4g+t4): conflict-free fragment loads
#define KSTR 132
#define VSTR 136   // banks (8*t4+g): conflict-free fragment loads
#define PSTR 68
#define NEG_INF -1e30f

struct Smem {
  float Q[BM][QSTR];      // tf32 bit patterns, pre-scaled by 1/sqrt(D)
  float K[BN][KSTR];      // tf32 bit patterns
  float V[BN][VSTR];      // tf32 bit patterns
  float P[NW][32][PSTR];  // tf32 bit patterns (per-warp softmax probs)
};

__device__ __forceinline__ uint32_t f2tf(float x) {
  uint32_t r;
  asm("cvt.rna.tf32.f32 %0, %1;" : "=r"(r) : "f"(x));
  return r;
}
__device__ __forceinline__ uint32_t fbits(float x) { return __float_as_uint(x); }

__device__ __forceinline__ void mma_tf32(float* d, const uint32_t* a, const uint32_t* b) {
  asm volatile(
      "mma.sync.aligned.m16n8k8.row.col.f32.tf32.tf32.f32 "
      "{%0,%1,%2,%3}, {%4,%5,%6,%7}, {%8,%9}, {%0,%1,%2,%3};"
      : "+f"(d[0]), "+f"(d[1]), "+f"(d[2]), "+f"(d[3])
      : "r"(a[0]), "r"(a[1]), "r"(a[2]), "r"(a[3]), "r"(b[0]), "r"(b[1]));
}

__global__ __launch_bounds__(NT, 1) void fa_fwd(
    const float* __restrict__ gq, const float* __restrict__ gk,
    const float* __restrict__ gv, float* __restrict__ gout) {
  extern __shared__ Smem sm[];
  Smem& s = sm[0];

  const int bh = blockIdx.y;
  const int qt = gridDim.x - 1 - blockIdx.x;  // heavy (long-causal) tiles first
  const int m0 = qt * BM;
  const size_t base = (size_t)bh * Ssz * Dsz;
  const float* q = gq + base;
  const float* k = gk + base;
  const float* v = gv + base;
  float* out = gout + base;

  const int tid  = threadIdx.x;
  const int warp = tid >> 5;
  const int lane = tid & 31;
  const int g    = lane >> 2;  // groupID 0..7
  const int t4   = lane & 3;   // thread-in-group 0..3

  const float scl = 0.08838834764831845f;  // 1/sqrt(128)

  // ---- Load Q tile (pre-scale, cvt to tf32) ----
  for (int i = tid; i < BM * (Dsz / 4); i += NT) {
    int r = i >> 5;
    int c = (i & 31) * 4;
    float4 qv = *(const float4*)&q[(size_t)(m0 + r) * Dsz + c];
    s.Q[r][c + 0] = __uint_as_float(f2tf(qv.x * scl));
    s.Q[r][c + 1] = __uint_as_float(f2tf(qv.y * scl));
    s.Q[r][c + 2] = __uint_as_float(f2tf(qv.z * scl));
    s.Q[r][c + 3] = __uint_as_float(f2tf(qv.w * scl));
  }

  // Accumulators: o[mtile][dtile][c-frag], softmax state per (mtile,row-half)
  float o[2][16][4];
  float mi[4] = {NEG_INF, NEG_INF, NEG_INF, NEG_INF};
  float li[4] = {0.f, 0.f, 0.f, 0.f};
#pragma unroll
  for (int a = 0; a < 2; a++)
#pragma unroll
    for (int b = 0; b < 16; b++)
#pragma unroll
      for (int c = 0; c < 4; c++) o[a][b][c] = 0.f;

  const int tmax = 2 * qt + 1;  // k-tiles [0, tmax], BN=BM/2

  for (int t = 0; t <= tmax; t++) {
    const int n0 = t * BN;
    __syncthreads();
    // ---- Load K,V tiles (cvt to tf32) ----
    for (int i = tid; i < BN * (Dsz / 4); i += NT) {
      int r = i >> 5;
      int c = (i & 31) * 4;
      float4 kv = *(const float4*)&k[(size_t)(n0 + r) * Dsz + c];
      s.K[r][c + 0] = __uint_as_float(f2tf(kv.x));
      s.K[r][c + 1] = __uint_as_float(f2tf(kv.y));
      s.K[r][c + 2] = __uint_as_float(f2tf(kv.z));
      s.K[r][c + 3] = __uint_as_float(f2tf(kv.w));
      float4 vv = *(const float4*)&v[(size_t)(n0 + r) * Dsz + c];
      s.V[r][c + 0] = __uint_as_float(f2tf(vv.x));
      s.V[r][c + 1] = __uint_as_float(f2tf(vv.y));
      s.V[r][c + 2] = __uint_as_float(f2tf(vv.z));
      s.V[r][c + 3] = __uint_as_float(f2tf(vv.w));
    }
    __syncthreads();

    // ---- S = Q @ K^T : 2 m-tiles x 8 n-tiles, K-dim 128 in 16 steps ----
    float sa[2][8][4];
#pragma unroll
    for (int a = 0; a < 2; a++)
#pragma unroll
      for (int b = 0; b < 8; b++)
#pragma unroll
        for (int c = 0; c < 4; c++) sa[a][b][c] = 0.f;

#pragma unroll
    for (int kt = 0; kt < 16; kt++) {
      const int kk = kt * 8;
      uint32_t afr[2][4];
#pragma unroll
      for (int mt = 0; mt < 2; mt++) {
        const int r = warp * 32 + mt * 16 + g;
        afr[mt][0] = fbits(s.Q[r][kk + t4]);
        afr[mt][1] = fbits(s.Q[r + 8][kk + t4]);
        afr[mt][2] = fbits(s.Q[r][kk + t4 + 4]);
        afr[mt][3] = fbits(s.Q[r + 8][kk + t4 + 4]);
      }
#pragma unroll
      for (int nt = 0; nt < 8; nt++) {
        uint32_t bfr[2];
        bfr[0] = fbits(s.K[nt * 8 + g][kk + t4]);
        bfr[1] = fbits(s.K[nt * 8 + g][kk + t4 + 4]);
        mma_tf32(sa[0][nt], afr[0], bfr);
        mma_tf32(sa[1][nt], afr[1], bfr);
      }
    }

    // ---- mask + online softmax per (mtile, row-half) ----
    const bool needmask = (n0 + BN - 1) > m0;
#pragma unroll
    for (int mt = 0; mt < 2; mt++) {
#pragma unroll
      for (int rr = 0; rr < 2; rr++) {
        const int st = mt * 2 + rr;
        const int grow = m0 + warp * 32 + mt * 16 + rr * 8 + g;
        // mask
        if (needmask) {
#pragma unroll
          for (int nt = 0; nt < 8; nt++) {
            int col = n0 + nt * 8 + 2 * t4;
            if (col > grow)     sa[mt][nt][rr * 2 + 0] = NEG_INF;
            if (col + 1 > grow) sa[mt][nt][rr * 2 + 1] = NEG_INF;
          }
        }
        // row max
        float mx = NEG_INF;
#pragma unroll
        for (int nt = 0; nt < 8; nt++) {
          mx = fmaxf(mx, sa[mt][nt][rr * 2 + 0]);
          mx = fmaxf(mx, sa[mt][nt][rr * 2 + 1]);
        }
        mx = fmaxf(mx, __shfl_xor_sync(0xffffffffu, mx, 1));
        mx = fmaxf(mx, __shfl_xor_sync(0xffffffffu, mx, 2));

        float mnew  = fmaxf(mi[st], mx);
        float alpha = __expf(mi[st] - mnew);
        float rs = 0.f;
#pragma unroll
        for (int nt = 0; nt < 8; nt++) {
          float p0 = __expf(sa[mt][nt][rr * 2 + 0] - mnew);
          float p1 = __expf(sa[mt][nt][rr * 2 + 1] - mnew);
          sa[mt][nt][rr * 2 + 0] = p0;
          sa[mt][nt][rr * 2 + 1] = p1;
          rs += p0 + p1;
        }
        rs += __shfl_xor_sync(0xffffffffu, rs, 1);
        rs += __shfl_xor_sync(0xffffffffu, rs, 2);

        li[st] = li[st] * alpha + rs;
        mi[st] = mnew;
#pragma unroll
        for (int dt = 0; dt < 16; dt++) {
          o[mt][dt][rr * 2 + 0] *= alpha;
          o[mt][dt][rr * 2 + 1] *= alpha;
        }
        // stage P (tf32) for the PV mma
        const int prow = mt * 16 + rr * 8 + g;
#pragma unroll
        for (int nt = 0; nt < 8; nt++) {
          float2 pp;
          pp.x = __uint_as_float(f2tf(sa[mt][nt][rr * 2 + 0]));
          pp.y = __uint_as_float(f2tf(sa[mt][nt][rr * 2 + 1]));
          *(float2*)&s.P[warp][prow][nt * 8 + 2 * t4] = pp;
        }
      }
    }
    __syncwarp();

    // ---- O += P @ V : K-dim 64 in 8 steps, 16 d-tiles ----
#pragma unroll
    for (int kt = 0; kt < 8; kt++) {
      const int kk = kt * 8;
      uint32_t afr[2][4];
#pragma unroll
      for (int mt = 0; mt < 2; mt++) {
        const int r = mt * 16 + g;
        afr[mt][0] = fbits(s.P[warp][r][kk + t4]);
        afr[mt][1] = fbits(s.P[warp][r + 8][kk + t4]);
        afr[mt][2] = fbits(s.P[warp][r][kk + t4 + 4]);
        afr[mt][3] = fbits(s.P[warp][r + 8][kk + t4 + 4]);
      }
#pragma unroll
      for (int dt = 0; dt < 16; dt++) {
        uint32_t bfr[2];
        bfr[0] = fbits(s.V[kk + t4][dt * 8 + g]);
        bfr[1] = fbits(s.V[kk + t4 + 4][dt * 8 + g]);
        mma_tf32(o[0][dt], afr[0], bfr);
        mma_tf32(o[1][dt], afr[1], bfr);
      }
    }
  }

  // ---- Epilogue: normalize, store ----
#pragma unroll
  for (int mt = 0; mt < 2; mt++) {
#pragma unroll
    for (int rr = 0; rr < 2; rr++) {
      const float inv = 1.0f / li[mt * 2 + rr];
      const size_t rowaddr = (size_t)(m0 + warp * 32 + mt * 16 + rr * 8 + g) * Dsz;
#pragma unroll
      for (int dt = 0; dt < 16; dt++) {
        float2 ov;
        ov.x = o[mt][dt][rr * 2 + 0] * inv;
        ov.y = o[mt][dt][rr * 2 + 1] * inv;
        *(float2*)&out[rowaddr + dt * 8 + 2 * t4] = ov;
      }
    }
  }
}

extern "C" void kernel_launch(void* const* d_in, const int* in_sizes, int n_in,
                              void* d_out, int out_size) {
  const int qkv_elems = Bsz * Hsz * Ssz * Dsz;
  const float* ptrs[3] = {nullptr, nullptr, nullptr};
  int np = 0;
  for (int i = 0; i < n_in && np < 3; i++) {
    if (in_sizes[i] == qkv_elems) ptrs[np++] = (const float*)d_in[i];
  }

  size_t smem_bytes = sizeof(Smem);
  cudaFuncSetAttribute(fa_fwd, cudaFuncAttributeMaxDynamicSharedMemorySize,
                       (int)smem_bytes);

  dim3 grid(Ssz / BM, Bsz * Hsz);
  fa_fwd<<<grid, NT, smem_bytes>>>(ptrs[0], ptrs[1], ptrs[2], (float*)d_out);
}